// round 15
// baseline (speedup 1.0000x reference)
#include <cuda_runtime.h>
#include <cuda_bf16.h>

// Problem constants (fixed shapes: x = (8,3,1024,1024) fp32, patch_size=24, stride=16)
namespace {
constexpr int Hh  = 1024;
constexpr int Ww  = 1024;
constexpr int Bb  = 8;
constexpr int Cc  = 3;
constexpr int PS  = 24;   // patch size
constexpr int ST  = 16;   // stride
constexpr int Mm  = 4;    // (PS - ST) / 2 reflect pad
constexpr int NH  = 64;   // 1024 / 16
constexpr int NW  = 64;
constexpr int ROWLEN = Ww + 2 * Mm;              // 1032 padded row
constexpr int THREADS = 384;
constexpr int PATCH_F4 = (PS * PS * Cc) / 4;     // 432 float4 per patch
constexpr long long MAIN_SZ = (long long)Bb * NH * NW * PS * PS * Cc; // 56,623,104
}

// One block = one (b, i, r): one padded source row feeds all 64 patches of
// patch-row i at within-patch row r.
//
// Shared memory holds the row CHANNEL-INTERLEAVED: sI[padded_col*3 + ch].
// Patch j's 72-float output run covers padded cols j*16 .. j*16+23, i.e.
// floats 48j .. 48j+71 — contiguous and 16B-aligned at every float4 boundary,
// so the emit loop is pure LDS.128 -> STG.128 (no /3, no scalar LDS).
//
// The channel transpose happens at load time in registers: each thread reads
// the same float4 column-group from all 3 channel rows (coalesced LDG.128 x3),
// permutes, and writes 3 STS.128 (lane stride 48B = 12 words -> all 32 banks
// covered once per phase: conflict-free).
__global__ __launch_bounds__(THREADS)
void patcher_kernel(const float* __restrict__ x, float4* __restrict__ out,
                    float* __restrict__ extras, int n_extra)
{
    __shared__ float sI[Cc * ROWLEN];   // interleaved: sI[col*3 + ch], 12384 B

    const int r = blockIdx.x;   // 0..23  within-patch row
    const int i = blockIdx.y;   // 0..63  patch row
    const int b = blockIdx.z;   // 0..7   batch
    const int t = threadIdx.x;

    // fused trailing (nH, nW) write — one designated block
    if (r == 0 && i == 0 && b == 0 && t < n_extra) {
        extras[t] = 64.0f;   // nH = nW = 64
    }

    // source row with reflect padding (reflect w/o edge repeat, jnp default)
    int v = i * ST + r - Mm;
    v = (v < 0) ? -v : v;
    v = (v > Hh - 1) ? 2 * (Hh - 1) - v : v;

    const float* row0 = x + (((size_t)(b * Cc + 0)) * Hh + (size_t)v) * Ww;
    const float* row1 = row0 + (size_t)Hh * Ww;
    const float* row2 = row1 + (size_t)Hh * Ww;

    if (t < 256) {
        // ---- main row load + register transpose: g = t ----
        const int g = t;
        float4 a   = reinterpret_cast<const float4*>(row0)[g];  // ch 0
        float4 bb4 = reinterpret_cast<const float4*>(row1)[g];  // ch 1
        float4 c   = reinterpret_cast<const float4*>(row2)[g];  // ch 2

        // interleaved run for padded cols Mm+4g .. Mm+4g+3:
        // [a0 b0 c0 a1 | b1 c1 a2 b2 | c2 a3 b3 c3]
        float* dst = &sI[(Mm + 4 * g) * Cc];   // float offset 12+12g -> 16B aligned
        reinterpret_cast<float4*>(dst)[0] = make_float4(a.x, bb4.x, c.x, a.y);
        reinterpret_cast<float4*>(dst)[1] = make_float4(bb4.y, c.y, a.z, bb4.z);
        reinterpret_cast<float4*>(dst)[2] = make_float4(c.z, a.w, bb4.w, c.w);
    } else if (t < 256 + Cc * 8) {
        // ---- reflect halo columns (4 left + 4 right per channel) ----
        int t2 = t - 256;
        int ch = t2 >> 3;
        int p  = t2 & 7;
        const float* rowp = (ch == 0) ? row0 : (ch == 1) ? row1 : row2;
        if (p < 4) {
            // padded col s = 3-p  <=>  orig col -(p+1) -> reflect -> col p+1
            sI[(3 - p) * Cc + ch] = rowp[p + 1];
        } else {
            int k = p - 3;  // 1..4 ; padded col 1027+k <=> orig 1023+k -> 1023-k
            sI[(Mm + (Ww - 1) + k) * Cc + ch] = rowp[(Ww - 1) - k];
        }
    }
    __syncthreads();

    // ---- emit: out[((b*64+i)*64 + j)*432 + r*18 + t18] (float4 units) ----
    const size_t base0 = ((size_t)(b * NH + i) * NW) * PATCH_F4 + (size_t)r * 18;
    const float4* sI4 = reinterpret_cast<const float4*>(sI);

    #pragma unroll
    for (int it = 0; it < 3; ++it) {
        int q   = t + it * THREADS;     // 0..1151
        int j   = q / 18;               // patch column 0..63
        int t18 = q - j * 18;           // float4 index inside this (p, r) run

        // patch j run starts at padded col 16j -> float 48j -> float4 12j
        float4 val = sI4[12 * j + t18];

        // streaming store: output is write-once; keep input resident in L2
        __stcs(&out[base0 + (size_t)j * PATCH_F4 + t18], val);
    }
}

extern "C" void kernel_launch(void* const* d_in, const int* in_sizes, int n_in,
                              void* d_out, int out_size)
{
    const float* x = (const float*)d_in[0];
    float* out = (float*)d_out;

    long long extra = (long long)out_size - MAIN_SZ;
    int n_extra = extra > 0 ? (int)extra : 0;

    dim3 grid(PS, NH, Bb);  // (24, 64, 8) = 12288 blocks
    patcher_kernel<<<grid, THREADS>>>(x, reinterpret_cast<float4*>(out),
                                      out + MAIN_SZ, n_extra);
}

// round 16
// speedup vs baseline: 1.1251x; 1.1251x over previous
#include <cuda_runtime.h>
#include <cuda_bf16.h>

// Problem constants (fixed shapes: x = (8,3,1024,1024) fp32, patch_size=24, stride=16)
namespace {
constexpr int Hh  = 1024;
constexpr int Ww  = 1024;
constexpr int Bb  = 8;
constexpr int Cc  = 3;
constexpr int PS  = 24;   // patch size
constexpr int ST  = 16;   // stride
constexpr int Mm  = 4;    // (PS - ST) / 2 reflect pad
constexpr int NH  = 64;   // 1024 / 16
constexpr int NW  = 64;
constexpr int ROWLEN = Ww + 2 * Mm;              // 1032 padded row
constexpr int THREADS = 384;
constexpr int PATCH_F4 = (PS * PS * Cc) / 4;     // 432 float4 per patch
constexpr long long MAIN_SZ = (long long)Bb * NH * NW * PS * PS * Cc; // 56,623,104
}

// One block = one (b, i, r-pair): TWO padded source rows feed all 64 patches
// of patch-row i at within-patch rows r0=2*rx and r1=2*rx+1.
//
// Rationale vs one-row blocks: doubles per-thread MLP (4 front-batched
// LDG.128), halves barrier count and block launch/drain tails, and uses all
// 384 threads in the load phase. __launch_bounds__(384,5) pins regs so 5
// CTAs/SM fit (smem 24.8KB x 5 = 124KB <= 228KB).
//
// Shared memory holds each row CHANNEL-INTERLEAVED: sI[row][col*3 + ch].
// Patch j's 72-float run covers floats 48j..48j+71 — contiguous, 16B-aligned
// at every float4 boundary, so emit is pure LDS.128 -> STG.128 (via __stcs:
// output is write-once; keep the input resident in L2).
__global__ __launch_bounds__(THREADS, 5)
void patcher_kernel(const float* __restrict__ x, float4* __restrict__ out,
                    float* __restrict__ extras, int n_extra)
{
    __shared__ float sI[2][Cc * ROWLEN];   // 2 x 12384 B

    const int rx = blockIdx.x;  // 0..11  row-pair
    const int i  = blockIdx.y;  // 0..63  patch row
    const int b  = blockIdx.z;  // 0..7   batch
    const int t  = threadIdx.x;

    // fused trailing (nH, nW) write — one designated block
    if (rx == 0 && i == 0 && b == 0 && t < n_extra) {
        extras[t] = 64.0f;   // nH = nW = 64
    }

    // two source rows with reflect padding (reflect w/o edge repeat)
    int vrow[2];
    #pragma unroll
    for (int rr = 0; rr < 2; ++rr) {
        int v = i * ST + (2 * rx + rr) - Mm;
        v = (v < 0) ? -v : v;
        v = (v > Hh - 1) ? 2 * (Hh - 1) - v : v;
        vrow[rr] = v;
    }

    const size_t plane = (size_t)Hh * Ww;
    const float* base = x + (size_t)b * Cc * plane;

    // ---- main loads: 2 rows x 3 ch x 256 float4 = 1536; 4 per thread ----
    #pragma unroll
    for (int it = 0; it < 4; ++it) {
        int idx = t + it * THREADS;        // 0..1535
        int rr  = idx >> 9 >> 0;           // idx/768 via: rr = idx >= 768
        rr = idx / 768;
        int rem = idx - rr * 768;          // 0..767
        int ch  = rem >> 8;                // /256
        int g   = rem & 255;
        const float4* src = reinterpret_cast<const float4*>(
            base + (size_t)ch * plane + (size_t)vrow[rr] * Ww);
        float4 a = src[g];
        // interleaved run for padded cols Mm+4g..Mm+4g+3 of row rr:
        // layout [a0 b0 c0 a1 | b1 c1 a2 b2 | c2 a3 b3 c3] is built by
        // writing this channel's 4 values to strided scalar slots — instead
        // keep the register-transpose: we need all 3 channels together.
        // Simpler: scalar STS x4 (channel-strided). See note below.
        float* dst = &sI[rr][(Mm + 4 * g) * Cc + ch];
        dst[0] = a.x; dst[3] = a.y; dst[6] = a.z; dst[9] = a.w;
    }

    // ---- reflect halo columns: 2 rows x 3 ch x 8 = 48 threads ----
    if (t < 48) {
        int rr = t >> 5 >> 0;  // t/24
        rr = t / 24;
        int t2 = t - rr * 24;
        int ch = t2 >> 3;
        int p  = t2 & 7;
        const float* rowp = base + (size_t)ch * plane + (size_t)vrow[rr] * Ww;
        if (p < 4) {
            // padded col s = 3-p  <=>  orig col -(p+1) -> reflect -> col p+1
            sI[rr][(3 - p) * Cc + ch] = rowp[p + 1];
        } else {
            int k = p - 3;  // 1..4 ; padded col 1027+k <=> orig 1023+k -> 1023-k
            sI[rr][(Mm + (Ww - 1) + k) * Cc + ch] = rowp[(Ww - 1) - k];
        }
    }
    __syncthreads();

    // ---- emit: out[((b*64+i)*64 + j)*432 + r*18 + t18] (float4 units) ----
    const size_t baseBI = ((size_t)(b * NH + i) * NW) * PATCH_F4;

    #pragma unroll
    for (int it = 0; it < 3; ++it) {
        int q   = t + it * THREADS;     // 0..1151
        int j   = q / 18;               // patch column 0..63
        int t18 = q - j * 18;           // float4 index inside the 72-float run
        size_t o = baseBI + (size_t)j * PATCH_F4 + t18;

        #pragma unroll
        for (int rr = 0; rr < 2; ++rr) {
            // patch j run starts at padded col 16j -> float 48j -> float4 12j
            float4 val = reinterpret_cast<const float4*>(sI[rr])[12 * j + t18];
            __stcs(&out[o + (size_t)(2 * rx + rr) * 18], val);
        }
    }
}

extern "C" void kernel_launch(void* const* d_in, const int* in_sizes, int n_in,
                              void* d_out, int out_size)
{
    const float* x = (const float*)d_in[0];
    float* out = (float*)d_out;

    long long extra = (long long)out_size - MAIN_SZ;
    int n_extra = extra > 0 ? (int)extra : 0;

    dim3 grid(PS / 2, NH, Bb);  // (12, 64, 8) = 6144 blocks
    patcher_kernel<<<grid, THREADS>>>(x, reinterpret_cast<float4*>(out),
                                      out + MAIN_SZ, n_extra);
}